// round 7
// baseline (speedup 1.0000x reference)
#include <cuda_runtime.h>

// ---------------------------------------------------------------------------
// Linformer block via mma.sync tf32 (HMMA; compute_103 PTX target).
// R7: 1 CTA/SM + 255 regs, 3-stage cp.async pipeline w/ single barrier per
// chunk, explicit fragment double-buffering across kk, x consumed raw
// (A-fragment CVT in-loop for GEMM1 only).
// ---------------------------------------------------------------------------

#define BDIM  8192
#define NTOK  4
#define CDIM  1024
#define HDIM  16
#define DDIM  64
#define PDIM  4
#define MTOK  (BDIM * NTOK)
#define SCALE_F 0.125f

__device__ float g_qkv[(size_t)MTOK * 3 * CDIM];
__device__ float g_ctx[(size_t)MTOK * CDIM];
__device__ float g_Wt [(size_t)3 * CDIM * CDIM];
__device__ float g_Wpt[(size_t)CDIM * CDIM];

// ------------------------------ GEMM config --------------------------------
#define BM 128
#define BN 128
#define BKC 32
#define NCH (CDIM / BKC)              // 32 k-chunks
#define RS 40                          // floats per smem row (LDS.64 conflict-free)
#define STAGE_FLOATS (256 * RS)        // 128 A rows + 128 B rows
#define STAGE_BYTES  (STAGE_FLOATS * 4)            // 40960
#define NSTAGE 3
#define SMEM_DYN (NSTAGE * STAGE_BYTES)            // 122880

__device__ __forceinline__ unsigned smem_u32(const void* p) {
    unsigned a;
    asm("{ .reg .u64 t; cvta.to.shared.u64 t, %1; cvt.u32.u64 %0, t; }"
        : "=r"(a) : "l"(p));
    return a;
}
__device__ __forceinline__ void cp16(unsigned saddr, const float* g) {
    asm volatile("cp.async.cg.shared.global [%0], [%1], 16;"
                 :: "r"(saddr), "l"(g) : "memory");
}
__device__ __forceinline__ void cp_commit() {
    asm volatile("cp.async.commit_group;" ::: "memory");
}
template<int N_>
__device__ __forceinline__ void cp_wait() {
    asm volatile("cp.async.wait_group %0;" :: "n"(N_) : "memory");
}
__device__ __forceinline__ unsigned f2tf(float f) {
    unsigned u; asm("cvt.rna.tf32.f32 %0, %1;" : "=r"(u) : "f"(f)); return u;
}
__device__ __forceinline__ float f2tf_f(float f) {
    return __uint_as_float(f2tf(f));
}
__device__ __forceinline__ void mma_tf32(float* d, const unsigned* a,
                                         const unsigned* b) {
    asm volatile(
        "mma.sync.aligned.m16n8k8.row.col.f32.tf32.tf32.f32 "
        "{%0,%1,%2,%3}, {%4,%5,%6,%7}, {%8,%9}, {%0,%1,%2,%3};"
        : "+f"(d[0]), "+f"(d[1]), "+f"(d[2]), "+f"(d[3])
        : "r"(a[0]), "r"(a[1]), "r"(a[2]), "r"(a[3]), "r"(b[0]), "r"(b[1]));
}

// ---------------------------------------------------------------------------
// C[M,Ncols] = A[M,1024] * B^T (+bias). B pre-rounded tf32, stored [Ncols,1024]
// row-major. CVTA: round A fragments in-loop (A raw fp32 in gmem).
// 128x128 tile, 8 warps (4m x 2n), warp tile 32x64.
// k-permutation: slice kk consumes logical k = kk*8 + 2q + {0,1}.
// ---------------------------------------------------------------------------
template<bool BIAS, bool CVTA>
__global__ __launch_bounds__(256, 1)
void tf32_gemm(const float* __restrict__ A, const float* __restrict__ B,
               const float* __restrict__ bias, float* __restrict__ C, int Ncols)
{
    extern __shared__ float smf[];
    const unsigned sb = smem_u32(smf);
    const int tid = threadIdx.x;
    const int m0 = blockIdx.y * BM;
    const int n0 = blockIdx.x * BN;

    const int w  = tid >> 5;
    const int wm = w & 3;
    const int wn = w >> 2;
    const int ln = tid & 31;
    const int g  = ln >> 2;
    const int q  = ln & 3;

    // cp.async slots: 4 A + 4 B 16B-segments per thread per chunk
    const float* gA[4]; unsigned sA[4];
    const float* gB[4]; unsigned sB[4];
    #pragma unroll
    for (int i = 0; i < 4; i++) {
        int idx = tid + i * 256;
        int row = idx >> 3, seg = idx & 7;
        gA[i] = A + (size_t)(m0 + row) * CDIM + seg * 4;
        sA[i] = sb + (row * RS + seg * 4) * 4;
        gB[i] = B + (size_t)(n0 + row) * CDIM + seg * 4;
        sB[i] = sb + ((128 + row) * RS + seg * 4) * 4;
    }

    #define ISSUE(ch) do { unsigned so = ((ch) % NSTAGE) * STAGE_BYTES;       \
        int ko = (ch) * BKC;                                                  \
        _Pragma("unroll") for (int i = 0; i < 4; i++) {                       \
            cp16(sA[i] + so, gA[i] + ko);                                     \
            cp16(sB[i] + so, gB[i] + ko); }                                    \
        cp_commit(); } while (0)

    float acc[2][8][4];
    #pragma unroll
    for (int mf = 0; mf < 2; mf++)
        #pragma unroll
        for (int nf = 0; nf < 8; nf++)
            #pragma unroll
            for (int i = 0; i < 4; i++) acc[mf][nf][i] = 0.f;

    ISSUE(0);
    ISSUE(1);

    const float* SaBase = smf + (wm * 32 + g) * RS;
    const float* SbBase = smf + (128 + wn * 64 + g) * RS;

    unsigned af[2][2][4];   // [buf][mf][frag]
    unsigned bf[2][8][2];   // [buf][nf][frag]

    #define LOADFRAG(buf, Sa, Sb, kkv) do {                                    \
        const int ko_ = (kkv) * 8 + 2 * q;                                     \
        float2 a0 = *reinterpret_cast<const float2*>((Sa) + ko_);              \
        float2 a1 = *reinterpret_cast<const float2*>((Sa) + 8 * RS + ko_);     \
        float2 a2 = *reinterpret_cast<const float2*>((Sa) + 16 * RS + ko_);    \
        float2 a3 = *reinterpret_cast<const float2*>((Sa) + 24 * RS + ko_);    \
        if (CVTA) {                                                            \
            af[buf][0][0] = f2tf(a0.x); af[buf][0][1] = f2tf(a1.x);            \
            af[buf][0][2] = f2tf(a0.y); af[buf][0][3] = f2tf(a1.y);            \
            af[buf][1][0] = f2tf(a2.x); af[buf][1][1] = f2tf(a3.x);            \
            af[buf][1][2] = f2tf(a2.y); af[buf][1][3] = f2tf(a3.y);            \
        } else {                                                               \
            af[buf][0][0] = __float_as_uint(a0.x);                             \
            af[buf][0][1] = __float_as_uint(a1.x);                             \
            af[buf][0][2] = __float_as_uint(a0.y);                             \
            af[buf][0][3] = __float_as_uint(a1.y);                             \
            af[buf][1][0] = __float_as_uint(a2.x);                             \
            af[buf][1][1] = __float_as_uint(a3.x);                             \
            af[buf][1][2] = __float_as_uint(a2.y);                             \
            af[buf][1][3] = __float_as_uint(a3.y);                             \
        }                                                                      \
        _Pragma("unroll") for (int nf = 0; nf < 8; nf++) {                     \
            float2 bv = *reinterpret_cast<const float2*>((Sb) + nf * 8 * RS + ko_); \
            bf[buf][nf][0] = __float_as_uint(bv.x);                            \
            bf[buf][nf][1] = __float_as_uint(bv.y);                            \
        } } while (0)

    for (int s = 0; s < NCH; s++) {
        if (s < NCH - 1) cp_wait<1>(); else cp_wait<0>();
        __syncthreads();
        if (s + 2 < NCH) ISSUE(s + 2);   // stage (s+2)%3 last read at chunk s-1

        const float* Sa = SaBase + (s % NSTAGE) * STAGE_FLOATS;
        const float* Sb = SbBase + (s % NSTAGE) * STAGE_FLOATS;

        LOADFRAG(0, Sa, Sb, 0);
        #pragma unroll
        for (int kk = 0; kk < 4; kk++) {
            const int cur = kk & 1;
            if (kk < 3) LOADFRAG(cur ^ 1, Sa, Sb, kk + 1);
            #pragma unroll
            for (int mf = 0; mf < 2; mf++)
                #pragma unroll
                for (int nf = 0; nf < 8; nf++)
                    mma_tf32(acc[mf][nf], af[cur][mf], bf[cur][nf]);
        }
    }

    // Epilogue
    const int mw = m0 + wm * 32 + g;
    const int nw = n0 + wn * 64 + 2 * q;
    #pragma unroll
    for (int mf = 0; mf < 2; mf++) {
        #pragma unroll
        for (int nf = 0; nf < 8; nf++) {
            int col = nw + nf * 8;
            float b0 = 0.f, b1 = 0.f;
            if (BIAS) { b0 = __ldg(bias + col); b1 = __ldg(bias + col + 1); }
            float* p0 = C + (size_t)(mw + mf * 16) * Ncols + col;
            float* p1 = p0 + (size_t)8 * Ncols;
            p0[0] = acc[mf][nf][0] + b0;  p0[1] = acc[mf][nf][1] + b1;
            p1[0] = acc[mf][nf][2] + b0;  p1[1] = acc[mf][nf][3] + b1;
        }
    }
    #undef ISSUE
    #undef LOADFRAG
}

// ---------------------------------------------------------------------------
// W_qkv transpose + tf32 round: [1024,3072] -> [3072,1024]
// ---------------------------------------------------------------------------
__global__ __launch_bounds__(256)
void transpose_kernel(const float* __restrict__ in, float* __restrict__ out)
{
    __shared__ float t[32][33];
    int bx = blockIdx.x * 32, by = blockIdx.y * 32;
    int x = threadIdx.x & 31, y = threadIdx.x >> 5;
    #pragma unroll
    for (int i = 0; i < 32; i += 8)
        t[y + i][x] = f2tf_f(in[(size_t)(by + y + i) * (3 * CDIM) + bx + x]);
    __syncthreads();
    #pragma unroll
    for (int i = 0; i < 32; i += 8)
        out[(size_t)(bx + y + i) * CDIM + by + x] = t[x][y + i];
}

// ---------------------------------------------------------------------------
// Elementwise tf32 round-copy (for W_proj)
// ---------------------------------------------------------------------------
__global__ __launch_bounds__(256)
void round_kernel(const float4* __restrict__ in, float4* __restrict__ out, int n4)
{
    for (int i = blockIdx.x * blockDim.x + threadIdx.x; i < n4;
         i += gridDim.x * blockDim.x) {
        float4 v = in[i];
        v.x = f2tf_f(v.x); v.y = f2tf_f(v.y);
        v.z = f2tf_f(v.z); v.w = f2tf_f(v.w);
        out[i] = v;
    }
}

// ---------------------------------------------------------------------------
// Middle kernel: one CTA per batch. ctx stored tf32-rounded (GEMM2 A operand).
// ---------------------------------------------------------------------------
__global__ __launch_bounds__(256)
void attn_mid_kernel(const float* __restrict__ W_E, const float* __restrict__ W_F,
                     float* __restrict__ attn_sel)
{
    __shared__ float s_q[NTOK][CDIM];
    __shared__ float s_klow[PDIM][CDIM];
    __shared__ float s_vlow[PDIM][CDIM];

    const int b = blockIdx.x;
    const int tid = threadIdx.x;
    const float* base = g_qkv + (size_t)b * NTOK * 3 * CDIM;

    for (int i = tid; i < NTOK * CDIM / 4; i += 256) {
        int n = i >> 8;
        int c4 = (i & 255) << 2;
        *reinterpret_cast<float4*>(&s_q[n][c4]) =
            *reinterpret_cast<const float4*>(base + (size_t)n * 3 * CDIM + c4);
    }
    float we[PDIM * NTOK], wf[PDIM * NTOK];
    #pragma unroll
    for (int i = 0; i < PDIM * NTOK; i++) { we[i] = __ldg(W_E + i); wf[i] = __ldg(W_F + i); }

    for (int c = tid; c < CDIM; c += 256) {
        float sk[PDIM] = {0.f,0.f,0.f,0.f}, sv[PDIM] = {0.f,0.f,0.f,0.f};
        #pragma unroll
        for (int n = 0; n < NTOK; n++) {
            float kn = base[(size_t)n * 3 * CDIM + CDIM + c];
            float vn = base[(size_t)n * 3 * CDIM + 2 * CDIM + c];
            #pragma unroll
            for (int p = 0; p < PDIM; p++) {
                sk[p] += kn * we[p * NTOK + n];
                sv[p] += vn * wf[p * NTOK + n];
            }
        }
        #pragma unroll
        for (int p = 0; p < PDIM; p++) { s_klow[p][c] = sk[p]; s_vlow[p][c] = sv[p]; }
    }
    __syncthreads();

    {
        int h = tid >> 4, gg = tid & 15;
        const float* krow = base + (size_t)2 * 3 * CDIM + CDIM + gg * DDIM;
        const float* qrow = &s_q[1][h * DDIM];
        float s = 0.f;
        #pragma unroll
        for (int d = 0; d < DDIM; d++) s += qrow[d] * krow[d];
        s *= SCALE_F;
        attn_sel[((size_t)b * HDIM + h) * HDIM + gg] = 1.f / (1.f + __expf(-s));
    }
    if (tid < HDIM * NTOK) {
        int h = tid >> 2, n = tid & 3;
        const float* qrow = &s_q[n][h * DDIM];
        float l[PDIM];
        #pragma unroll
        for (int p = 0; p < PDIM; p++) {
            float s = 0.f;
            #pragma unroll
            for (int d = 0; d < DDIM; d++) s += qrow[d] * s_klow[p][h * DDIM + d];
            l[p] = s * SCALE_F;
        }
        float mx = fmaxf(fmaxf(l[0], l[1]), fmaxf(l[2], l[3]));
        float e[PDIM], sum = 0.f;
        #pragma unroll
        for (int p = 0; p < PDIM; p++) { e[p] = __expf(l[p] - mx); sum += e[p]; }
        float inv = 1.f / sum;
        #pragma unroll
        for (int p = 0; p < PDIM; p++) e[p] *= inv;
        float* orow = g_ctx + ((size_t)b * NTOK + n) * CDIM + h * DDIM;
        #pragma unroll
        for (int d = 0; d < DDIM; d++) {
            float o = 0.f;
            #pragma unroll
            for (int p = 0; p < PDIM; p++) o += e[p] * s_vlow[p][h * DDIM + d];
            orow[d] = f2tf_f(o);
        }
    }
}

// ---------------------------------------------------------------------------
extern "C" void kernel_launch(void* const* d_in, const int* in_sizes, int n_in,
                              void* d_out, int out_size)
{
    (void)in_sizes; (void)n_in; (void)out_size;
    const float* x      = (const float*)d_in[0];
    const float* W_qkv  = (const float*)d_in[1];
    const float* W_proj = (const float*)d_in[2];
    const float* b_proj = (const float*)d_in[3];
    const float* W_E    = (const float*)d_in[4];
    const float* W_F    = (const float*)d_in[5];

    float* out      = (float*)d_out;
    float* attn_sel = out + (size_t)MTOK * CDIM;

    float *qkv_ptr, *ctx_ptr, *wt_ptr, *wpt_ptr;
    cudaGetSymbolAddress((void**)&qkv_ptr, g_qkv);
    cudaGetSymbolAddress((void**)&ctx_ptr, g_ctx);
    cudaGetSymbolAddress((void**)&wt_ptr,  g_Wt);
    cudaGetSymbolAddress((void**)&wpt_ptr, g_Wpt);

    cudaFuncSetAttribute((const void*)tf32_gemm<false, true>,
                         cudaFuncAttributeMaxDynamicSharedMemorySize, SMEM_DYN);
    cudaFuncSetAttribute((const void*)tf32_gemm<true, false>,
                         cudaFuncAttributeMaxDynamicSharedMemorySize, SMEM_DYN);

    // Weight prep (x consumed raw; ctx pre-rounded by middle kernel)
    transpose_kernel<<<dim3(3 * CDIM / 32, CDIM / 32), 256>>>(W_qkv, wt_ptr);
    round_kernel<<<1024, 256>>>((const float4*)W_proj, (float4*)wpt_ptr,
                                CDIM * CDIM / 4);

    // K1: qkv = x @ Wt^T  (CVT A in-loop)
    tf32_gemm<false, true><<<dim3(3 * CDIM / BN, MTOK / BM), 256, SMEM_DYN>>>(
        x, wt_ptr, nullptr, qkv_ptr, 3 * CDIM);

    // K2: attention middle
    attn_mid_kernel<<<BDIM, 256>>>(W_E, W_F, attn_sel);

    // K3: out = ctx @ Wpt^T + b
    tf32_gemm<true, false><<<dim3(CDIM / BN, MTOK / BM), 256, SMEM_DYN>>>(
        ctx_ptr, wpt_ptr, b_proj, out, CDIM);
}

// round 8
// speedup vs baseline: 1.3953x; 1.3953x over previous
#include <cuda_runtime.h>

// ---------------------------------------------------------------------------
// Linformer block via mma.sync tf32 (HMMA; compute_103 PTX target).
// R8: GEMMs = R6 config (2 CTA/SM, 2-stage cp.async, LDS.64 fragments,
// operands pre-rounded). Middle rewritten as two smem-free warp-per-(b,h)
// kernels (butterfly-shuffle reductions, coalesced float2 traffic).
// ---------------------------------------------------------------------------

#define BDIM  8192
#define NTOK  4
#define CDIM  1024
#define HDIM  16
#define DDIM  64
#define PDIM  4
#define MTOK  (BDIM * NTOK)
#define SCALE_F 0.125f

__device__ float g_qkv[(size_t)MTOK * 3 * CDIM];
__device__ float g_ctx[(size_t)MTOK * CDIM];
__device__ float g_xtf[(size_t)MTOK * CDIM];
__device__ float g_Wt [(size_t)3 * CDIM * CDIM];
__device__ float g_Wpt[(size_t)CDIM * CDIM];

// ------------------------------ GEMM config --------------------------------
#define BM 128
#define BN 128
#define BKC 32
#define NCH (CDIM / BKC)
#define RS 40
#define STAGE_FLOATS (256 * RS)
#define STAGE_BYTES  (STAGE_FLOATS * 4)
#define SMEM_DYN     (2 * STAGE_BYTES)   // 81920

__device__ __forceinline__ unsigned smem_u32(const void* p) {
    unsigned a;
    asm("{ .reg .u64 t; cvta.to.shared.u64 t, %1; cvt.u32.u64 %0, t; }"
        : "=r"(a) : "l"(p));
    return a;
}
__device__ __forceinline__ void cp16(unsigned saddr, const float* g) {
    asm volatile("cp.async.cg.shared.global [%0], [%1], 16;"
                 :: "r"(saddr), "l"(g) : "memory");
}
__device__ __forceinline__ void cp_commit() {
    asm volatile("cp.async.commit_group;" ::: "memory");
}
template<int N_>
__device__ __forceinline__ void cp_wait() {
    asm volatile("cp.async.wait_group %0;" :: "n"(N_) : "memory");
}
__device__ __forceinline__ unsigned f2tf(float f) {
    unsigned u; asm("cvt.rna.tf32.f32 %0, %1;" : "=r"(u) : "f"(f)); return u;
}
__device__ __forceinline__ float f2tf_f(float f) {
    return __uint_as_float(f2tf(f));
}
__device__ __forceinline__ void mma_tf32(float* d, const unsigned* a,
                                         const unsigned* b) {
    asm volatile(
        "mma.sync.aligned.m16n8k8.row.col.f32.tf32.tf32.f32 "
        "{%0,%1,%2,%3}, {%4,%5,%6,%7}, {%8,%9}, {%0,%1,%2,%3};"
        : "+f"(d[0]), "+f"(d[1]), "+f"(d[2]), "+f"(d[3])
        : "r"(a[0]), "r"(a[1]), "r"(a[2]), "r"(a[3]), "r"(b[0]), "r"(b[1]));
}

// ---------------------------------------------------------------------------
// C[M,Ncols] = A[M,1024] * B^T (+bias); A,B pre-rounded tf32.
// 128x128 tile, 8 warps (4m x 2n), 2-stage cp.async, LDS.64 fragments.
// ---------------------------------------------------------------------------
template<bool BIAS>
__global__ __launch_bounds__(256, 2)
void tf32_gemm(const float* __restrict__ A, const float* __restrict__ B,
               const float* __restrict__ bias, float* __restrict__ C, int Ncols)
{
    extern __shared__ float smf[];
    const unsigned sb = smem_u32(smf);
    const int tid = threadIdx.x;
    const int m0 = blockIdx.y * BM;
    const int n0 = blockIdx.x * BN;

    const int w  = tid >> 5;
    const int wm = w & 3;
    const int wn = w >> 2;
    const int ln = tid & 31;
    const int g  = ln >> 2;
    const int q  = ln & 3;

    const float* gA[4]; unsigned sA[4];
    const float* gB[4]; unsigned sB[4];
    #pragma unroll
    for (int i = 0; i < 4; i++) {
        int idx = tid + i * 256;
        int row = idx >> 3, seg = idx & 7;
        gA[i] = A + (size_t)(m0 + row) * CDIM + seg * 4;
        sA[i] = sb + (row * RS + seg * 4) * 4;
        gB[i] = B + (size_t)(n0 + row) * CDIM + seg * 4;
        sB[i] = sb + ((128 + row) * RS + seg * 4) * 4;
    }

    #define ISSUE(ch) do { unsigned so = ((ch) & 1) * STAGE_BYTES;            \
        int ko = (ch) * BKC;                                                  \
        _Pragma("unroll") for (int i = 0; i < 4; i++) {                       \
            cp16(sA[i] + so, gA[i] + ko);                                     \
            cp16(sB[i] + so, gB[i] + ko); }                                    \
        cp_commit(); } while (0)

    float acc[2][8][4];
    #pragma unroll
    for (int mf = 0; mf < 2; mf++)
        #pragma unroll
        for (int nf = 0; nf < 8; nf++)
            #pragma unroll
            for (int i = 0; i < 4; i++) acc[mf][nf][i] = 0.f;

    ISSUE(0);

    const float* SaBase = smf + (wm * 32 + g) * RS;
    const float* SbBase = smf + (128 + wn * 64 + g) * RS;

    for (int s = 0; s < NCH; s++) {
        if (s + 1 < NCH) { ISSUE(s + 1); cp_wait<1>(); }
        else             { cp_wait<0>(); }
        __syncthreads();

        const float* Sa = SaBase + (s & 1) * STAGE_FLOATS;
        const float* Sb = SbBase + (s & 1) * STAGE_FLOATS;

        #pragma unroll
        for (int kk = 0; kk < 4; kk++) {
            const int ko = kk * 8 + 2 * q;
            float2 a0 = *reinterpret_cast<const float2*>(Sa + ko);
            float2 a1 = *reinterpret_cast<const float2*>(Sa + 8 * RS + ko);
            float2 a2 = *reinterpret_cast<const float2*>(Sa + 16 * RS + ko);
            float2 a3 = *reinterpret_cast<const float2*>(Sa + 24 * RS + ko);
            unsigned af[2][4];
            af[0][0] = __float_as_uint(a0.x); af[0][1] = __float_as_uint(a1.x);
            af[0][2] = __float_as_uint(a0.y); af[0][3] = __float_as_uint(a1.y);
            af[1][0] = __float_as_uint(a2.x); af[1][1] = __float_as_uint(a3.x);
            af[1][2] = __float_as_uint(a2.y); af[1][3] = __float_as_uint(a3.y);

            unsigned bfm[8][2];
            #pragma unroll
            for (int nf = 0; nf < 8; nf++) {
                float2 bv = *reinterpret_cast<const float2*>(Sb + nf * 8 * RS + ko);
                bfm[nf][0] = __float_as_uint(bv.x);
                bfm[nf][1] = __float_as_uint(bv.y);
            }
            #pragma unroll
            for (int mf = 0; mf < 2; mf++)
                #pragma unroll
                for (int nf = 0; nf < 8; nf++)
                    mma_tf32(acc[mf][nf], af[mf], bfm[nf]);
        }
        __syncthreads();
    }

    const int mw = m0 + wm * 32 + g;
    const int nw = n0 + wn * 64 + 2 * q;
    #pragma unroll
    for (int mf = 0; mf < 2; mf++) {
        #pragma unroll
        for (int nf = 0; nf < 8; nf++) {
            int col = nw + nf * 8;
            float b0 = 0.f, b1 = 0.f;
            if (BIAS) { b0 = __ldg(bias + col); b1 = __ldg(bias + col + 1); }
            float* p0 = C + (size_t)(mw + mf * 16) * Ncols + col;
            float* p1 = p0 + (size_t)8 * Ncols;
            p0[0] = acc[mf][nf][0] + b0;  p0[1] = acc[mf][nf][1] + b1;
            p1[0] = acc[mf][nf][2] + b0;  p1[1] = acc[mf][nf][3] + b1;
        }
    }
    #undef ISSUE
}

// ---------------------------------------------------------------------------
// W_qkv transpose + tf32 round
// ---------------------------------------------------------------------------
__global__ __launch_bounds__(256)
void transpose_kernel(const float* __restrict__ in, float* __restrict__ out)
{
    __shared__ float t[32][33];
    int bx = blockIdx.x * 32, by = blockIdx.y * 32;
    int x = threadIdx.x & 31, y = threadIdx.x >> 5;
    #pragma unroll
    for (int i = 0; i < 32; i += 8)
        t[y + i][x] = f2tf_f(in[(size_t)(by + y + i) * (3 * CDIM) + bx + x]);
    __syncthreads();
    #pragma unroll
    for (int i = 0; i < 32; i += 8)
        out[(size_t)(bx + y + i) * CDIM + by + x] = t[x][y + i];
}

__global__ __launch_bounds__(256)
void round_kernel(const float4* __restrict__ in, float4* __restrict__ out, int n4)
{
    for (int i = blockIdx.x * blockDim.x + threadIdx.x; i < n4;
         i += gridDim.x * blockDim.x) {
        float4 v = in[i];
        v.x = f2tf_f(v.x); v.y = f2tf_f(v.y);
        v.z = f2tf_f(v.z); v.w = f2tf_f(v.w);
        out[i] = v;
    }
}

// ---------------------------------------------------------------------------
// Middle main: one warp per (b,h). Lane owns d = {2*lane, 2*lane+1}.
// k_low/v_low in registers; 16 logits reduced via 5 bfly shuffles; softmax;
// ctx written tf32-rounded.  No smem, no block barriers.
// ---------------------------------------------------------------------------
__global__ __launch_bounds__(256)
void attn_core_kernel(const float* __restrict__ W_E, const float* __restrict__ W_F)
{
    const int wglob = blockIdx.x * 8 + (threadIdx.x >> 5);
    const int b = wglob >> 4;
    const int h = wglob & 15;
    const int lane = threadIdx.x & 31;

    const float* base = g_qkv + (size_t)b * NTOK * 3 * CDIM + h * DDIM + 2 * lane;

    float2 qv[NTOK], kv[NTOK], vv[NTOK];
    #pragma unroll
    for (int n = 0; n < NTOK; n++) {
        const float* r = base + (size_t)n * 3 * CDIM;
        qv[n] = *reinterpret_cast<const float2*>(r);
        kv[n] = *reinterpret_cast<const float2*>(r + CDIM);
        vv[n] = *reinterpret_cast<const float2*>(r + 2 * CDIM);
    }

    float we[16], wf[16];
    #pragma unroll
    for (int i = 0; i < 16; i++) { we[i] = __ldg(W_E + i); wf[i] = __ldg(W_F + i); }

    float2 kl[PDIM], vl[PDIM];
    #pragma unroll
    for (int p = 0; p < PDIM; p++) {
        kl[p].x = kl[p].y = vl[p].x = vl[p].y = 0.f;
        #pragma unroll
        for (int n = 0; n < NTOK; n++) {
            kl[p].x += kv[n].x * we[p * 4 + n];
            kl[p].y += kv[n].y * we[p * 4 + n];
            vl[p].x += vv[n].x * wf[p * 4 + n];
            vl[p].y += vv[n].y * wf[p * 4 + n];
        }
    }

    // 16 partial logits (n,p), reduce across lanes
    float lg[16];
    #pragma unroll
    for (int n = 0; n < NTOK; n++)
        #pragma unroll
        for (int p = 0; p < PDIM; p++)
            lg[n * 4 + p] = qv[n].x * kl[p].x + qv[n].y * kl[p].y;
    #pragma unroll
    for (int off = 16; off >= 1; off >>= 1)
        #pragma unroll
        for (int i = 0; i < 16; i++)
            lg[i] += __shfl_xor_sync(0xFFFFFFFFu, lg[i], off);

    // softmax over p (per n), SCALE applied to logits
    float aw[16];
    #pragma unroll
    for (int n = 0; n < NTOK; n++) {
        float l0 = lg[n * 4] * SCALE_F, l1 = lg[n * 4 + 1] * SCALE_F;
        float l2 = lg[n * 4 + 2] * SCALE_F, l3 = lg[n * 4 + 3] * SCALE_F;
        float mx = fmaxf(fmaxf(l0, l1), fmaxf(l2, l3));
        float e0 = __expf(l0 - mx), e1 = __expf(l1 - mx);
        float e2 = __expf(l2 - mx), e3 = __expf(l3 - mx);
        float inv = 1.f / (e0 + e1 + e2 + e3);
        aw[n * 4] = e0 * inv; aw[n * 4 + 1] = e1 * inv;
        aw[n * 4 + 2] = e2 * inv; aw[n * 4 + 3] = e3 * inv;
    }

    float* cbase = g_ctx + (size_t)b * NTOK * CDIM + h * DDIM + 2 * lane;
    #pragma unroll
    for (int n = 0; n < NTOK; n++) {
        float ox = 0.f, oy = 0.f;
        #pragma unroll
        for (int p = 0; p < PDIM; p++) {
            ox += aw[n * 4 + p] * vl[p].x;
            oy += aw[n * 4 + p] * vl[p].y;
        }
        float2 o; o.x = f2tf_f(ox); o.y = f2tf_f(oy);
        *reinterpret_cast<float2*>(cbase + (size_t)n * CDIM) = o;
    }
}

// ---------------------------------------------------------------------------
// attn_sel: one warp per (b,h): sigmoid(SCALE * q[b,h,tok1,:] . k[b,g,tok2,:])
// ---------------------------------------------------------------------------
__global__ __launch_bounds__(256)
void attn_sel_kernel(float* __restrict__ attn_sel)
{
    const int wglob = blockIdx.x * 8 + (threadIdx.x >> 5);
    const int b = wglob >> 4;
    const int h = wglob & 15;
    const int lane = threadIdx.x & 31;

    const float* base = g_qkv + (size_t)b * NTOK * 3 * CDIM;
    float2 qv = *reinterpret_cast<const float2*>(
        base + (size_t)1 * 3 * CDIM + h * DDIM + 2 * lane);

    const float* k2 = base + (size_t)2 * 3 * CDIM + CDIM + 2 * lane;
    float s[16];
    #pragma unroll
    for (int gg = 0; gg < 16; gg++) {
        float2 kv = *reinterpret_cast<const float2*>(k2 + gg * DDIM);
        s[gg] = qv.x * kv.x + qv.y * kv.y;
    }
    #pragma unroll
    for (int off = 16; off >= 1; off >>= 1)
        #pragma unroll
        for (int i = 0; i < 16; i++)
            s[i] += __shfl_xor_sync(0xFFFFFFFFu, s[i], off);

    if (lane < 16) {
        float v = s[lane] * SCALE_F;
        attn_sel[((size_t)b * HDIM + h) * HDIM + lane] = 1.f / (1.f + __expf(-v));
    }
}

// ---------------------------------------------------------------------------
extern "C" void kernel_launch(void* const* d_in, const int* in_sizes, int n_in,
                              void* d_out, int out_size)
{
    (void)in_sizes; (void)n_in; (void)out_size;
    const float* x      = (const float*)d_in[0];
    const float* W_qkv  = (const float*)d_in[1];
    const float* W_proj = (const float*)d_in[2];
    const float* b_proj = (const float*)d_in[3];
    const float* W_E    = (const float*)d_in[4];
    const float* W_F    = (const float*)d_in[5];

    float* out      = (float*)d_out;
    float* attn_sel = out + (size_t)MTOK * CDIM;

    float *qkv_ptr, *ctx_ptr, *xtf_ptr, *wt_ptr, *wpt_ptr;
    cudaGetSymbolAddress((void**)&qkv_ptr, g_qkv);
    cudaGetSymbolAddress((void**)&ctx_ptr, g_ctx);
    cudaGetSymbolAddress((void**)&xtf_ptr, g_xtf);
    cudaGetSymbolAddress((void**)&wt_ptr,  g_Wt);
    cudaGetSymbolAddress((void**)&wpt_ptr, g_Wpt);

    cudaFuncSetAttribute(tf32_gemm<false>,
                         cudaFuncAttributeMaxDynamicSharedMemorySize, SMEM_DYN);
    cudaFuncSetAttribute(tf32_gemm<true>,
                         cudaFuncAttributeMaxDynamicSharedMemorySize, SMEM_DYN);

    // operand pre-rounding
    transpose_kernel<<<dim3(3 * CDIM / 32, CDIM / 32), 256>>>(W_qkv, wt_ptr);
    round_kernel<<<1024, 256>>>((const float4*)W_proj, (float4*)wpt_ptr,
                                CDIM * CDIM / 4);
    round_kernel<<<8192, 256>>>((const float4*)x, (float4*)xtf_ptr,
                                MTOK * CDIM / 4);

    // K1: qkv = xtf @ Wt^T
    tf32_gemm<false><<<dim3(3 * CDIM / BN, MTOK / BM), 256, SMEM_DYN>>>(
        xtf_ptr, wt_ptr, nullptr, qkv_ptr, 3 * CDIM);

    // K2: middle (warp-parallel, smem-free)
    attn_core_kernel<<<BDIM * HDIM / 8, 256>>>(W_E, W_F);
    attn_sel_kernel<<<BDIM * HDIM / 8, 256>>>(attn_sel);

    // K3: out = ctx @ Wpt^T + b
    tf32_gemm<true><<<dim3(CDIM / BN, MTOK / BM), 256, SMEM_DYN>>>(
        ctx_ptr, wpt_ptr, b_proj, out, CDIM);
}

// round 10
// speedup vs baseline: 1.4234x; 1.0201x over previous
#include <cuda_runtime.h>

// ---------------------------------------------------------------------------
// Linformer block via mma.sync tf32 (HMMA; compute_103 PTX target).
// R9: GEMM inner loop rebuilt — ld.shared.v2.b32 straight into fragment
// registers (no packing MOVs), immediate-offset LDS addressing, single
// __syncthreads per k-chunk (2-stage, ISSUE after barrier).
// Middle = R8 warp-parallel smem-free kernels.
// ---------------------------------------------------------------------------

#define BDIM  8192
#define NTOK  4
#define CDIM  1024
#define HDIM  16
#define DDIM  64
#define PDIM  4
#define MTOK  (BDIM * NTOK)
#define SCALE_F 0.125f

__device__ float g_qkv[(size_t)MTOK * 3 * CDIM];
__device__ float g_ctx[(size_t)MTOK * CDIM];
__device__ float g_xtf[(size_t)MTOK * CDIM];
__device__ float g_Wt [(size_t)3 * CDIM * CDIM];
__device__ float g_Wpt[(size_t)CDIM * CDIM];

// ------------------------------ GEMM config --------------------------------
#define BM 128
#define BN 128
#define BKC 32
#define NCH (CDIM / BKC)
#define RS 40
#define STAGE_FLOATS (256 * RS)
#define STAGE_BYTES  (STAGE_FLOATS * 4)
#define SMEM_DYN     (2 * STAGE_BYTES)   // 81920

__device__ __forceinline__ unsigned smem_u32(const void* p) {
    unsigned a;
    asm("{ .reg .u64 t; cvta.to.shared.u64 t, %1; cvt.u32.u64 %0, t; }"
        : "=r"(a) : "l"(p));
    return a;
}
__device__ __forceinline__ void cp16(unsigned saddr, const float* g) {
    asm volatile("cp.async.cg.shared.global [%0], [%1], 16;"
                 :: "r"(saddr), "l"(g) : "memory");
}
__device__ __forceinline__ void cp_commit() {
    asm volatile("cp.async.commit_group;" ::: "memory");
}
template<int N_>
__device__ __forceinline__ void cp_wait() {
    asm volatile("cp.async.wait_group %0;" :: "n"(N_) : "memory");
}
__device__ __forceinline__ unsigned f2tf(float f) {
    unsigned u; asm("cvt.rna.tf32.f32 %0, %1;" : "=r"(u) : "f"(f)); return u;
}
__device__ __forceinline__ float f2tf_f(float f) {
    return __uint_as_float(f2tf(f));
}
// v2 LDS straight into two fragment registers (pair allocated by ptxas)
__device__ __forceinline__ void lds64(unsigned& lo, unsigned& hi, unsigned addr) {
    asm volatile("ld.shared.v2.b32 {%0,%1}, [%2];"
                 : "=r"(lo), "=r"(hi) : "r"(addr));
}
__device__ __forceinline__ void mma_tf32(float* d, const unsigned* a,
                                         const unsigned* b) {
    asm volatile(
        "mma.sync.aligned.m16n8k8.row.col.f32.tf32.tf32.f32 "
        "{%0,%1,%2,%3}, {%4,%5,%6,%7}, {%8,%9}, {%0,%1,%2,%3};"
        : "+f"(d[0]), "+f"(d[1]), "+f"(d[2]), "+f"(d[3])
        : "r"(a[0]), "r"(a[1]), "r"(a[2]), "r"(a[3]), "r"(b[0]), "r"(b[1]));
}

// ---------------------------------------------------------------------------
// C[M,Ncols] = A[M,1024] * B^T (+bias); A,B pre-rounded tf32.
// 128x128 tile, 8 warps (4m x 2n), 2-stage cp.async, 1 barrier/chunk.
// k-permutation: slice kk consumes logical k = kk*8 + 2q + {0,1}.
// ---------------------------------------------------------------------------
template<bool BIAS>
__global__ __launch_bounds__(256, 2)
void tf32_gemm(const float* __restrict__ A, const float* __restrict__ B,
               const float* __restrict__ bias, float* __restrict__ C, int Ncols)
{
    extern __shared__ float smf[];
    const unsigned sb = smem_u32(smf);
    const int tid = threadIdx.x;
    const int m0 = blockIdx.y * BM;
    const int n0 = blockIdx.x * BN;

    const int w  = tid >> 5;
    const int wm = w & 3;
    const int wn = w >> 2;
    const int ln = tid & 31;
    const int g  = ln >> 2;
    const int q  = ln & 3;

    // cp.async slots: 4 A + 4 B 16B segments per thread per chunk
    const float* gA[4]; unsigned sA[4];
    const float* gB[4]; unsigned sB[4];
    #pragma unroll
    for (int i = 0; i < 4; i++) {
        int idx = tid + i * 256;
        int row = idx >> 3, seg = idx & 7;
        gA[i] = A + (size_t)(m0 + row) * CDIM + seg * 4;
        sA[i] = sb + (row * RS + seg * 4) * 4;
        gB[i] = B + (size_t)(n0 + row) * CDIM + seg * 4;
        sB[i] = sb + ((128 + row) * RS + seg * 4) * 4;
    }

    #define ISSUE(ch) do { unsigned so = ((ch) & 1) * STAGE_BYTES;            \
        int ko = (ch) * BKC;                                                  \
        _Pragma("unroll") for (int i = 0; i < 4; i++) {                       \
            cp16(sA[i] + so, gA[i] + ko);                                     \
            cp16(sB[i] + so, gB[i] + ko); }                                    \
        cp_commit(); } while (0)

    float acc[2][8][4];
    #pragma unroll
    for (int mf = 0; mf < 2; mf++)
        #pragma unroll
        for (int nf = 0; nf < 8; nf++)
            #pragma unroll
            for (int i = 0; i < 4; i++) acc[mf][nf][i] = 0.f;

    ISSUE(0);

    // Per-thread fragment base byte addresses (stage 0)
    const unsigned aA0 = sb + ((wm * 32 + g) * RS + 2 * q) * 4;       // row g
    const unsigned aA1 = aA0 + 8 * RS * 4;                            // row g+8
    const unsigned aA2 = aA0 + 16 * RS * 4;                           // row g+16
    const unsigned aA3 = aA0 + 24 * RS * 4;                           // row g+24
    unsigned aB[8];
    #pragma unroll
    for (int nf = 0; nf < 8; nf++)
        aB[nf] = sb + ((128 + wn * 64 + nf * 8 + g) * RS + 2 * q) * 4;

    for (int s = 0; s < NCH; s++) {
        cp_wait<0>();
        __syncthreads();
        if (s + 1 < NCH) ISSUE(s + 1);   // writes other stage; safe post-barrier

        const unsigned sof = (s & 1) * STAGE_BYTES;

        #pragma unroll
        for (int kk = 0; kk < 4; kk++) {
            const unsigned ko = sof + kk * 32;   // +kk*8 floats
            unsigned af[2][4], bf[8][2];
            lds64(af[0][0], af[0][2], aA0 + ko);
            lds64(af[0][1], af[0][3], aA1 + ko);
            lds64(af[1][0], af[1][2], aA2 + ko);
            lds64(af[1][1], af[1][3], aA3 + ko);
            #pragma unroll
            for (int nf = 0; nf < 8; nf++)
                lds64(bf[nf][0], bf[nf][1], aB[nf] + ko);
            #pragma unroll
            for (int mf = 0; mf < 2; mf++)
                #pragma unroll
                for (int nf = 0; nf < 8; nf++)
                    mma_tf32(acc[mf][nf], af[mf], bf[nf]);
        }
    }

    const int mw = m0 + wm * 32 + g;
    const int nw = n0 + wn * 64 + 2 * q;
    #pragma unroll
    for (int mf = 0; mf < 2; mf++) {
        #pragma unroll
        for (int nf = 0; nf < 8; nf++) {
            int col = nw + nf * 8;
            float b0 = 0.f, b1 = 0.f;
            if (BIAS) { b0 = __ldg(bias + col); b1 = __ldg(bias + col + 1); }
            float* p0 = C + (size_t)(mw + mf * 16) * Ncols + col;
            float* p1 = p0 + (size_t)8 * Ncols;
            p0[0] = acc[mf][nf][0] + b0;  p0[1] = acc[mf][nf][1] + b1;
            p1[0] = acc[mf][nf][2] + b0;  p1[1] = acc[mf][nf][3] + b1;
        }
    }
    #undef ISSUE
}

// ---------------------------------------------------------------------------
// W_qkv transpose + tf32 round
// ---------------------------------------------------------------------------
__global__ __launch_bounds__(256)
void transpose_kernel(const float* __restrict__ in, float* __restrict__ out)
{
    __shared__ float t[32][33];
    int bx = blockIdx.x * 32, by = blockIdx.y * 32;
    int x = threadIdx.x & 31, y = threadIdx.x >> 5;
    #pragma unroll
    for (int i = 0; i < 32; i += 8)
        t[y + i][x] = f2tf_f(in[(size_t)(by + y + i) * (3 * CDIM) + bx + x]);
    __syncthreads();
    #pragma unroll
    for (int i = 0; i < 32; i += 8)
        out[(size_t)(bx + y + i) * CDIM + by + x] = t[x][y + i];
}

__global__ __launch_bounds__(256)
void round_kernel(const float4* __restrict__ in, float4* __restrict__ out, int n4)
{
    for (int i = blockIdx.x * blockDim.x + threadIdx.x; i < n4;
         i += gridDim.x * blockDim.x) {
        float4 v = in[i];
        v.x = f2tf_f(v.x); v.y = f2tf_f(v.y);
        v.z = f2tf_f(v.z); v.w = f2tf_f(v.w);
        out[i] = v;
    }
}

// ---------------------------------------------------------------------------
// Middle main: one warp per (b,h); lane owns d = {2*lane, 2*lane+1}.
// ---------------------------------------------------------------------------
__global__ __launch_bounds__(256)
void attn_core_kernel(const float* __restrict__ W_E, const float* __restrict__ W_F)
{
    const int wglob = blockIdx.x * 8 + (threadIdx.x >> 5);
    const int b = wglob >> 4;
    const int h = wglob & 15;
    const int lane = threadIdx.x & 31;

    const float* base = g_qkv + (size_t)b * NTOK * 3 * CDIM + h * DDIM + 2 * lane;

    float2 qv[NTOK], kv[NTOK], vv[NTOK];
    #pragma unroll
    for (int n = 0; n < NTOK; n++) {
        const float* r = base + (size_t)n * 3 * CDIM;
        qv[n] = *reinterpret_cast<const float2*>(r);
        kv[n] = *reinterpret_cast<const float2*>(r + CDIM);
        vv[n] = *reinterpret_cast<const float2*>(r + 2 * CDIM);
    }

    float we[16], wf[16];
    #pragma unroll
    for (int i = 0; i < 16; i++) { we[i] = __ldg(W_E + i); wf[i] = __ldg(W_F + i); }

    float2 kl[PDIM], vl[PDIM];
    #pragma unroll
    for (int p = 0; p < PDIM; p++) {
        kl[p].x = kl[p].y = vl[p].x = vl[p].y = 0.f;
        #pragma unroll
        for (int n = 0; n < NTOK; n++) {
            kl[p].x += kv[n].x * we[p * 4 + n];
            kl[p].y += kv[n].y * we[p * 4 + n];
            vl[p].x += vv[n].x * wf[p * 4 + n];
            vl[p].y += vv[n].y * wf[p * 4 + n];
        }
    }

    float lg[16];
    #pragma unroll
    for (int n = 0; n < NTOK; n++)
        #pragma unroll
        for (int p = 0; p < PDIM; p++)
            lg[n * 4 + p] = qv[n].x * kl[p].x + qv[n].y * kl[p].y;
    #pragma unroll
    for (int off = 16; off >= 1; off >>= 1)
        #pragma unroll
        for (int i = 0; i < 16; i++)
            lg[i] += __shfl_xor_sync(0xFFFFFFFFu, lg[i], off);

    float aw[16];
    #pragma unroll
    for (int n = 0; n < NTOK; n++) {
        float l0 = lg[n * 4] * SCALE_F, l1 = lg[n * 4 + 1] * SCALE_F;
        float l2 = lg[n * 4 + 2] * SCALE_F, l3 = lg[n * 4 + 3] * SCALE_F;
        float mx = fmaxf(fmaxf(l0, l1), fmaxf(l2, l3));
        float e0 = __expf(l0 - mx), e1 = __expf(l1 - mx);
        float e2 = __expf(l2 - mx), e3 = __expf(l3 - mx);
        float inv = 1.f / (e0 + e1 + e2 + e3);
        aw[n * 4] = e0 * inv; aw[n * 4 + 1] = e1 * inv;
        aw[n * 4 + 2] = e2 * inv; aw[n * 4 + 3] = e3 * inv;
    }

    float* cbase = g_ctx + (size_t)b * NTOK * CDIM + h * DDIM + 2 * lane;
    #pragma unroll
    for (int n = 0; n < NTOK; n++) {
        float ox = 0.f, oy = 0.f;
        #pragma unroll
        for (int p = 0; p < PDIM; p++) {
            ox += aw[n * 4 + p] * vl[p].x;
            oy += aw[n * 4 + p] * vl[p].y;
        }
        float2 o; o.x = f2tf_f(ox); o.y = f2tf_f(oy);
        *reinterpret_cast<float2*>(cbase + (size_t)n * CDIM) = o;
    }
}

// ---------------------------------------------------------------------------
// attn_sel: one warp per (b,h)
// ---------------------------------------------------------------------------
__global__ __launch_bounds__(256)
void attn_sel_kernel(float* __restrict__ attn_sel)
{
    const int wglob = blockIdx.x * 8 + (threadIdx.x >> 5);
    const int b = wglob >> 4;
    const int h = wglob & 15;
    const int lane = threadIdx.x & 31;

    const float* base = g_qkv + (size_t)b * NTOK * 3 * CDIM;
    float2 qv = *reinterpret_cast<const float2*>(
        base + (size_t)1 * 3 * CDIM + h * DDIM + 2 * lane);

    const float* k2 = base + (size_t)2 * 3 * CDIM + CDIM + 2 * lane;
    float s[16];
    #pragma unroll
    for (int gg = 0; gg < 16; gg++) {
        float2 kv = *reinterpret_cast<const float2*>(k2 + gg * DDIM);
        s[gg] = qv.x * kv.x + qv.y * kv.y;
    }
    #pragma unroll
    for (int off = 16; off >= 1; off >>= 1)
        #pragma unroll
        for (int i = 0; i < 16; i++)
            s[i] += __shfl_xor_sync(0xFFFFFFFFu, s[i], off);

    if (lane < 16) {
        float v = s[lane] * SCALE_F;
        attn_sel[((size_t)b * HDIM + h) * HDIM + lane] = 1.f / (1.f + __expf(-v));
    }
}

// ---------------------------------------------------------------------------
extern "C" void kernel_launch(void* const* d_in, const int* in_sizes, int n_in,
                              void* d_out, int out_size)
{
    (void)in_sizes; (void)n_in; (void)out_size;
    const float* x      = (const float*)d_in[0];
    const float* W_qkv  = (const float*)d_in[1];
    const float* W_proj = (const float*)d_in[2];
    const float* b_proj = (const float*)d_in[3];
    const float* W_E    = (const float*)d_in[4];
    const float* W_F    = (const float*)d_in[5];

    float* out      = (float*)d_out;
    float* attn_sel = out + (size_t)MTOK * CDIM;

    float *qkv_ptr, *ctx_ptr, *xtf_ptr, *wt_ptr, *wpt_ptr;
    cudaGetSymbolAddress((void**)&qkv_ptr, g_qkv);
    cudaGetSymbolAddress((void**)&ctx_ptr, g_ctx);
    cudaGetSymbolAddress((void**)&xtf_ptr, g_xtf);
    cudaGetSymbolAddress((void**)&wt_ptr,  g_Wt);
    cudaGetSymbolAddress((void**)&wpt_ptr, g_Wpt);

    cudaFuncSetAttribute(tf32_gemm<false>,
                         cudaFuncAttributeMaxDynamicSharedMemorySize, SMEM_DYN);
    cudaFuncSetAttribute(tf32_gemm<true>,
                         cudaFuncAttributeMaxDynamicSharedMemorySize, SMEM_DYN);

    transpose_kernel<<<dim3(3 * CDIM / 32, CDIM / 32), 256>>>(W_qkv, wt_ptr);
    round_kernel<<<1024, 256>>>((const float4*)W_proj, (float4*)wpt_ptr,
                                CDIM * CDIM / 4);
    round_kernel<<<8192, 256>>>((const float4*)x, (float4*)xtf_ptr,
                                MTOK * CDIM / 4);

    tf32_gemm<false><<<dim3(3 * CDIM / BN, MTOK / BM), 256, SMEM_DYN>>>(
        xtf_ptr, wt_ptr, nullptr, qkv_ptr, 3 * CDIM);

    attn_core_kernel<<<BDIM * HDIM / 8, 256>>>(W_E, W_F);
    attn_sel_kernel<<<BDIM * HDIM / 8, 256>>>(attn_sel);

    tf32_gemm<true><<<dim3(CDIM / BN, MTOK / BM), 256, SMEM_DYN>>>(
        ctx_ptr, wpt_ptr, b_proj, out, CDIM);
}

// round 13
// speedup vs baseline: 1.5073x; 1.0589x over previous
#include <cuda_runtime.h>

// ---------------------------------------------------------------------------
// Linformer block via mma.sync tf32 (HMMA; compute_103 PTX target).
// R11: fragment loads via ldmatrix.x4 (standard tf32 fragment layout),
// RS=36 (conflict-free LDSM phases). Otherwise identical to R10 best.
// ---------------------------------------------------------------------------

#define BDIM  8192
#define NTOK  4
#define CDIM  1024
#define HDIM  16
#define DDIM  64
#define PDIM  4
#define MTOK  (BDIM * NTOK)
#define SCALE_F 0.125f

__device__ float g_qkv[(size_t)MTOK * 3 * CDIM];
__device__ float g_ctx[(size_t)MTOK * CDIM];
__device__ float g_xtf[(size_t)MTOK * CDIM];
__device__ float g_Wt [(size_t)3 * CDIM * CDIM];
__device__ float g_Wpt[(size_t)CDIM * CDIM];

// ------------------------------ GEMM config --------------------------------
#define BM 128
#define BN 128
#define BKC 32
#define NCH (CDIM / BKC)
#define RS 36                          // 144B rows: LDSM + STS.128 conflict-free
#define STAGE_FLOATS (256 * RS)
#define STAGE_BYTES  (STAGE_FLOATS * 4)   // 36864
#define SMEM_DYN     (2 * STAGE_BYTES)    // 73728

__device__ __forceinline__ unsigned smem_u32(const void* p) {
    unsigned a;
    asm("{ .reg .u64 t; cvta.to.shared.u64 t, %1; cvt.u32.u64 %0, t; }"
        : "=r"(a) : "l"(p));
    return a;
}
__device__ __forceinline__ void cp16(unsigned saddr, const float* g) {
    asm volatile("cp.async.cg.shared.global [%0], [%1], 16;"
                 :: "r"(saddr), "l"(g) : "memory");
}
__device__ __forceinline__ void cp_commit() {
    asm volatile("cp.async.commit_group;" ::: "memory");
}
template<int N_>
__device__ __forceinline__ void cp_wait() {
    asm volatile("cp.async.wait_group %0;" :: "n"(N_) : "memory");
}
__device__ __forceinline__ unsigned f2tf(float f) {
    unsigned u; asm("cvt.rna.tf32.f32 %0, %1;" : "=r"(u) : "f"(f)); return u;
}
__device__ __forceinline__ float f2tf_f(float f) {
    return __uint_as_float(f2tf(f));
}
__device__ __forceinline__ void ldsm4(unsigned& r0, unsigned& r1,
                                      unsigned& r2, unsigned& r3, unsigned a) {
    asm volatile("ldmatrix.sync.aligned.m8n8.x4.shared.b16 {%0,%1,%2,%3}, [%4];"
                 : "=r"(r0), "=r"(r1), "=r"(r2), "=r"(r3) : "r"(a));
}
__device__ __forceinline__ void mma_tf32(float* d, const unsigned* a,
                                         const unsigned* b) {
    asm volatile(
        "mma.sync.aligned.m16n8k8.row.col.f32.tf32.tf32.f32 "
        "{%0,%1,%2,%3}, {%4,%5,%6,%7}, {%8,%9}, {%0,%1,%2,%3};"
        : "+f"(d[0]), "+f"(d[1]), "+f"(d[2]), "+f"(d[3])
        : "r"(a[0]), "r"(a[1]), "r"(a[2]), "r"(a[3]), "r"(b[0]), "r"(b[1]));
}

// ---------------------------------------------------------------------------
// C[M,Ncols] = A[M,1024] * B^T (+bias); A,B pre-rounded tf32.
// 128x128 tile, 8 warps (4m x 2n), 2-stage cp.async, 1 barrier/chunk,
// LDSM.x4 fragment loads (standard m16n8k8 tf32 layout).
// ---------------------------------------------------------------------------
template<bool BIAS>
__global__ __launch_bounds__(256, 2)
void tf32_gemm(const float* __restrict__ A, const float* __restrict__ B,
               const float* __restrict__ bias, float* __restrict__ C, int Ncols)
{
    extern __shared__ float smf[];
    const unsigned sb = smem_u32(smf);
    const int tid = threadIdx.x;
    const int m0 = blockIdx.y * BM;
    const int n0 = blockIdx.x * BN;

    const int w  = tid >> 5;
    const int wm = w & 3;
    const int wn = w >> 2;
    const int ln = tid & 31;
    const int g  = ln >> 2;
    const int q  = ln & 3;

    // cp.async slots: 4 A + 4 B 16B segments per thread per chunk
    const float* gA[4]; unsigned sA[4];
    const float* gB[4]; unsigned sB[4];
    #pragma unroll
    for (int i = 0; i < 4; i++) {
        int idx = tid + i * 256;
        int row = idx >> 3, seg = idx & 7;
        gA[i] = A + (size_t)(m0 + row) * CDIM + seg * 4;
        sA[i] = sb + (row * RS + seg * 4) * 4;
        gB[i] = B + (size_t)(n0 + row) * CDIM + seg * 4;
        sB[i] = sb + ((128 + row) * RS + seg * 4) * 4;
    }

    #define ISSUE(ch) do { unsigned so = ((ch) & 1) * STAGE_BYTES;            \
        int ko = (ch) * BKC;                                                  \
        _Pragma("unroll") for (int i = 0; i < 4; i++) {                       \
            cp16(sA[i] + so, gA[i] + ko);                                     \
            cp16(sB[i] + so, gB[i] + ko); }                                    \
        cp_commit(); } while (0)

    float acc[2][8][4];
    #pragma unroll
    for (int mf = 0; mf < 2; mf++)
        #pragma unroll
        for (int nf = 0; nf < 8; nf++)
            #pragma unroll
            for (int i = 0; i < 4; i++) acc[mf][nf][i] = 0.f;

    ISSUE(0);

    // LDSM per-lane base addresses (stage 0, kk=0):
    // A x4 (per mf): lanes 0-15 -> rows (ln&15), k bytes 0..15;
    //                lanes 16-31 -> same rows, k bytes 16..31.
    const unsigned aA = sb + ((wm * 32 + (ln & 15)) * RS) * 4 + ((ln & 16) ? 16 : 0);
    // B x4 (per j-pair): lanes 0-7 rows j*16+(ln&7) kb0; 8-15 same rows kb16;
    //                    16-23 rows j*16+8+(ln&7) kb0; 24-31 same kb16.
    const unsigned aB = sb + ((128 + wn * 64 + (ln & 7) + ((ln & 16) ? 8 : 0)) * RS) * 4
                        + ((ln & 8) ? 16 : 0);

    for (int s = 0; s < NCH; s++) {
        cp_wait<0>();
        __syncthreads();
        if (s + 1 < NCH) ISSUE(s + 1);

        const unsigned sof = (s & 1) * STAGE_BYTES;

        #pragma unroll
        for (int kk = 0; kk < 4; kk++) {
            const unsigned ko = sof + kk * 32;
            unsigned a0[4], a1[4], br[4][4];
            ldsm4(a0[0], a0[1], a0[2], a0[3], aA + ko);                 // rows 0-15
            ldsm4(a1[0], a1[1], a1[2], a1[3], aA + ko + 16 * RS * 4);   // rows 16-31
            #pragma unroll
            for (int j = 0; j < 4; j++)
                ldsm4(br[j][0], br[j][1], br[j][2], br[j][3],
                      aB + ko + j * (16 * RS * 4));
            #pragma unroll
            for (int j = 0; j < 4; j++) {
                mma_tf32(acc[0][2 * j],     a0, &br[j][0]);
                mma_tf32(acc[0][2 * j + 1], a0, &br[j][2]);
                mma_tf32(acc[1][2 * j],     a1, &br[j][0]);
                mma_tf32(acc[1][2 * j + 1], a1, &br[j][2]);
            }
        }
    }

    // Epilogue: lane (g,q): c0=D[g][2q], c1=D[g][2q+1], c2/c3 at row g+8
    const int mw = m0 + wm * 32 + g;
    const int nw = n0 + wn * 64 + 2 * q;
    #pragma unroll
    for (int mf = 0; mf < 2; mf++) {
        #pragma unroll
        for (int nf = 0; nf < 8; nf++) {
            int col = nw + nf * 8;
            float b0 = 0.f, b1 = 0.f;
            if (BIAS) { b0 = __ldg(bias + col); b1 = __ldg(bias + col + 1); }
            float* p0 = C + (size_t)(mw + mf * 16) * Ncols + col;
            float* p1 = p0 + (size_t)8 * Ncols;
            p0[0] = acc[mf][nf][0] + b0;  p0[1] = acc[mf][nf][1] + b1;
            p1[0] = acc[mf][nf][2] + b0;  p1[1] = acc[mf][nf][3] + b1;
        }
    }
    #undef ISSUE
}

// ---------------------------------------------------------------------------
// W_qkv transpose + tf32 round
// ---------------------------------------------------------------------------
__global__ __launch_bounds__(256)
void transpose_kernel(const float* __restrict__ in, float* __restrict__ out)
{
    __shared__ float t[32][33];
    int bx = blockIdx.x * 32, by = blockIdx.y * 32;
    int x = threadIdx.x & 31, y = threadIdx.x >> 5;
    #pragma unroll
    for (int i = 0; i < 32; i += 8)
        t[y + i][x] = f2tf_f(in[(size_t)(by + y + i) * (3 * CDIM) + bx + x]);
    __syncthreads();
    #pragma unroll
    for (int i = 0; i < 32; i += 8)
        out[(size_t)(bx + y + i) * CDIM + by + x] = t[x][y + i];
}

__global__ __launch_bounds__(256)
void round_kernel(const float4* __restrict__ in, float4* __restrict__ out, int n4)
{
    for (int i = blockIdx.x * blockDim.x + threadIdx.x; i < n4;
         i += gridDim.x * blockDim.x) {
        float4 v = in[i];
        v.x = f2tf_f(v.x); v.y = f2tf_f(v.y);
        v.z = f2tf_f(v.z); v.w = f2tf_f(v.w);
        out[i] = v;
    }
}

// ---------------------------------------------------------------------------
// Middle main: one warp per (b,h); lane owns d = {2*lane, 2*lane+1}.
// ---------------------------------------------------------------------------
__global__ __launch_bounds__(256)
void attn_core_kernel(const float* __restrict__ W_E, const float* __restrict__ W_F)
{
    const int wglob = blockIdx.x * 8 + (threadIdx.x >> 5);
    const int b = wglob >> 4;
    const int h = wglob & 15;
    const int lane = threadIdx.x & 31;

    const float* base = g_qkv + (size_t)b * NTOK * 3 * CDIM + h * DDIM + 2 * lane;

    float2 qv[NTOK], kv[NTOK], vv[NTOK];
    #pragma unroll
    for (int n = 0; n < NTOK; n++) {
        const float* r = base + (size_t)n * 3 * CDIM;
        qv[n] = *reinterpret_cast<const float2*>(r);
        kv[n] = *reinterpret_cast<const float2*>(r + CDIM);
        vv[n] = *reinterpret_cast<const float2*>(r + 2 * CDIM);
    }

    float we[16], wf[16];
    #pragma unroll
    for (int i = 0; i < 16; i++) { we[i] = __ldg(W_E + i); wf[i] = __ldg(W_F + i); }

    float2 kl[PDIM], vl[PDIM];
    #pragma unroll
    for (int p = 0; p < PDIM; p++) {
        kl[p].x = kl[p].y = vl[p].x = vl[p].y = 0.f;
        #pragma unroll
        for (int n = 0; n < NTOK; n++) {
            kl[p].x += kv[n].x * we[p * 4 + n];
            kl[p].y += kv[n].y * we[p * 4 + n];
            vl[p].x += vv[n].x * wf[p * 4 + n];
            vl[p].y += vv[n].y * wf[p * 4 + n];
        }
    }

    float lg[16];
    #pragma unroll
    for (int n = 0; n < NTOK; n++)
        #pragma unroll
        for (int p = 0; p < PDIM; p++)
            lg[n * 4 + p] = qv[n].x * kl[p].x + qv[n].y * kl[p].y;
    #pragma unroll
    for (int off = 16; off >= 1; off >>= 1)
        #pragma unroll
        for (int i = 0; i < 16; i++)
            lg[i] += __shfl_xor_sync(0xFFFFFFFFu, lg[i], off);

    float aw[16];
    #pragma unroll
    for (int n = 0; n < NTOK; n++) {
        float l0 = lg[n * 4] * SCALE_F, l1 = lg[n * 4 + 1] * SCALE_F;
        float l2 = lg[n * 4 + 2] * SCALE_F, l3 = lg[n * 4 + 3] * SCALE_F;
        float mx = fmaxf(fmaxf(l0, l1), fmaxf(l2, l3));
        float e0 = __expf(l0 - mx), e1 = __expf(l1 - mx);
        float e2 = __expf(l2 - mx), e3 = __expf(l3 - mx);
        float inv = 1.f / (e0 + e1 + e2 + e3);
        aw[n * 4] = e0 * inv; aw[n * 4 + 1] = e1 * inv;
        aw[n * 4 + 2] = e2 * inv; aw[n * 4 + 3] = e3 * inv;
    }

    float* cbase = g_ctx + (size_t)b * NTOK * CDIM + h * DDIM + 2 * lane;
    #pragma unroll
    for (int n = 0; n < NTOK; n++) {
        float ox = 0.f, oy = 0.f;
        #pragma unroll
        for (int p = 0; p < PDIM; p++) {
            ox += aw[n * 4 + p] * vl[p].x;
            oy += aw[n * 4 + p] * vl[p].y;
        }
        float2 o; o.x = f2tf_f(ox); o.y = f2tf_f(oy);
        *reinterpret_cast<float2*>(cbase + (size_t)n * CDIM) = o;
    }
}

// ---------------------------------------------------------------------------
// attn_sel: one warp per (b,h)
// ---------------------------------------------------------------------------
__global__ __launch_bounds__(256)
void attn_sel_kernel(float* __restrict__ attn_sel)
{
    const int wglob = blockIdx.x * 8 + (threadIdx.x >> 5);
    const int b = wglob >> 4;
    const int h = wglob & 15;
    const int lane = threadIdx.x & 31;

    const float* base = g_qkv + (size_t)b * NTOK * 3 * CDIM;
    float2 qv = *reinterpret_cast<const float2*>(
        base + (size_t)1 * 3 * CDIM + h * DDIM + 2 * lane);

    const float* k2 = base + (size_t)2 * 3 * CDIM + CDIM + 2 * lane;
    float s[16];
    #pragma unroll
    for (int gg = 0; gg < 16; gg++) {
        float2 kv = *reinterpret_cast<const float2*>(k2 + gg * DDIM);
        s[gg] = qv.x * kv.x + qv.y * kv.y;
    }
    #pragma unroll
    for (int off = 16; off >= 1; off >>= 1)
        #pragma unroll
        for (int i = 0; i < 16; i++)
            s[i] += __shfl_xor_sync(0xFFFFFFFFu, s[i], off);

    if (lane < 16) {
        float v = s[lane] * SCALE_F;
        attn_sel[((size_t)b * HDIM + h) * HDIM + lane] = 1.f / (1.f + __expf(-v));
    }
}

// ---------------------------------------------------------------------------
extern "C" void kernel_launch(void* const* d_in, const int* in_sizes, int n_in,
                              void* d_out, int out_size)
{
    (void)in_sizes; (void)n_in; (void)out_size;
    const float* x      = (const float*)d_in[0];
    const float* W_qkv  = (const float*)d_in[1];
    const float* W_proj = (const float*)d_in[2];
    const float* b_proj = (const float*)d_in[3];
    const float* W_E    = (const float*)d_in[4];
    const float* W_F    = (const float*)d_in[5];

    float* out      = (float*)d_out;
    float* attn_sel = out + (size_t)MTOK * CDIM;

    float *qkv_ptr, *ctx_ptr, *xtf_ptr, *wt_ptr, *wpt_ptr;
    cudaGetSymbolAddress((void**)&qkv_ptr, g_qkv);
    cudaGetSymbolAddress((void**)&ctx_ptr, g_ctx);
    cudaGetSymbolAddress((void**)&xtf_ptr, g_xtf);
    cudaGetSymbolAddress((void**)&wt_ptr,  g_Wt);
    cudaGetSymbolAddress((void**)&wpt_ptr, g_Wpt);

    cudaFuncSetAttribute(tf32_gemm<false>,
                         cudaFuncAttributeMaxDynamicSharedMemorySize, SMEM_DYN);
    cudaFuncSetAttribute(tf32_gemm<true>,
                         cudaFuncAttributeMaxDynamicSharedMemorySize, SMEM_DYN);

    transpose_kernel<<<dim3(3 * CDIM / 32, CDIM / 32), 256>>>(W_qkv, wt_ptr);
    round_kernel<<<1024, 256>>>((const float4*)W_proj, (float4*)wpt_ptr,
                                CDIM * CDIM / 4);
    round_kernel<<<8192, 256>>>((const float4*)x, (float4*)xtf_ptr,
                                MTOK * CDIM / 4);

    tf32_gemm<false><<<dim3(3 * CDIM / BN, MTOK / BM), 256, SMEM_DYN>>>(
        xtf_ptr, wt_ptr, nullptr, qkv_ptr, 3 * CDIM);

    attn_core_kernel<<<BDIM * HDIM / 8, 256>>>(W_E, W_F);
    attn_sel_kernel<<<BDIM * HDIM / 8, 256>>>(attn_sel);

    tf32_gemm<true><<<dim3(CDIM / BN, MTOK / BM), 256, SMEM_DYN>>>(
        ctx_ptr, wpt_ptr, b_proj, out, CDIM);
}